// round 6
// baseline (speedup 1.0000x reference)
#include <cuda_runtime.h>
#include <math.h>

#define BATCH   2
#define SEQ     4096
#define DMODEL  512
#define NHEADS  8
#define DK      64
#define DFF     2048
#define ROWS    (BATCH * SEQ)   // 8192
#define EPS     1e-5f

// ---------------- scratch (static device globals; no allocs allowed) ----------
__device__ float g_Q  [ROWS * DMODEL];
__device__ float g_K  [ROWS * DMODEL];
__device__ float g_V  [ROWS * DMODEL];
__device__ float g_AO [ROWS * DMODEL];
__device__ float g_X1 [ROWS * DMODEL];
__device__ float g_FFH[ROWS * DFF];

// ---------------- tf32 helpers ------------------------------------------------
__device__ __forceinline__ float f2tf32(float x) {
    unsigned r;
    asm("cvt.rna.tf32.f32 %0, %1;" : "=r"(r) : "f"(x));
    return __uint_as_float(r);
}

__device__ __forceinline__ void mma_tf32(float* c,
                                         float a0, float a1, float a2, float a3,
                                         float b0, float b1)
{
    asm volatile(
        "mma.sync.aligned.m16n8k8.row.col.f32.tf32.tf32.f32 "
        "{%0,%1,%2,%3}, {%4,%5,%6,%7}, {%8,%9}, {%0,%1,%2,%3};"
        : "+f"(c[0]), "+f"(c[1]), "+f"(c[2]), "+f"(c[3])
        : "r"(__float_as_uint(a0)), "r"(__float_as_uint(a1)),
          "r"(__float_as_uint(a2)), "r"(__float_as_uint(a3)),
          "r"(__float_as_uint(b0)), "r"(__float_as_uint(b1)));
}

// ---------------- tf32 tensor-core GEMM, reg-staged double buffer -------------
// block tile 128x128x32, 256 threads, warps 2(m) x 4(n), warp tile 64x32
#define TBM 128
#define TBN 128
#define TBK 32
#define ASTR (TBK + 4)    // 36  -> A-frag pattern conflict-free
#define BSTR (TBN + 8)    // 136 -> B-frag pattern conflict-free

__global__ void __launch_bounds__(256)
gemm_tc(const float* __restrict__ A, const float* __restrict__ B,
        const float* __restrict__ bias, float* __restrict__ C,
        int M, int N, int K, int relu)
{
    __shared__ float As[TBM][ASTR];
    __shared__ float Bs[TBK][BSTR];

    const int tid  = threadIdx.x;
    const int warp = tid >> 5, lane = tid & 31;
    const int wm = warp >> 2;          // 0..1
    const int wn = warp & 3;           // 0..3
    const int r    = lane >> 2;        // 0..7
    const int cg   = lane & 3;         // 0..3
    const int row0 = blockIdx.y * TBM;
    const int col0 = blockIdx.x * TBN;

    // per-thread load coords (A: 128x32 = 1024 fl4; B: 32x128 = 1024 fl4)
    int aRow[4], aCol[4], bRow[4], bCol[4];
    #pragma unroll
    for (int i = 0; i < 4; i++) {
        int l = tid + i * 256;
        aRow[i] = l >> 3;  aCol[i] = (l & 7) * 4;
        bRow[i] = l >> 5;  bCol[i] = (l & 31) * 4;
    }

    float4 ra[4], rb[4];
    #pragma unroll
    for (int i = 0; i < 4; i++) {
        ra[i] = *reinterpret_cast<const float4*>(&A[(size_t)(row0 + aRow[i]) * K + aCol[i]]);
        rb[i] = *reinterpret_cast<const float4*>(&B[(size_t)bRow[i] * N + col0 + bCol[i]]);
    }

    float acc[4][4][4] = {};           // [mfrag][nfrag][c0..c3]

    for (int k0 = 0; k0 < K; k0 += TBK) {
        // commit staged tile to smem (tf32-rounded)
        #pragma unroll
        for (int i = 0; i < 4; i++) {
            *reinterpret_cast<float4*>(&As[aRow[i]][aCol[i]]) =
                make_float4(f2tf32(ra[i].x), f2tf32(ra[i].y), f2tf32(ra[i].z), f2tf32(ra[i].w));
            *reinterpret_cast<float4*>(&Bs[bRow[i]][bCol[i]]) =
                make_float4(f2tf32(rb[i].x), f2tf32(rb[i].y), f2tf32(rb[i].z), f2tf32(rb[i].w));
        }
        __syncthreads();

        // prefetch next tile into registers (overlaps MMA below)
        if (k0 + TBK < K) {
            #pragma unroll
            for (int i = 0; i < 4; i++) {
                ra[i] = *reinterpret_cast<const float4*>(
                    &A[(size_t)(row0 + aRow[i]) * K + k0 + TBK + aCol[i]]);
                rb[i] = *reinterpret_cast<const float4*>(
                    &B[(size_t)(k0 + TBK + bRow[i]) * N + col0 + bCol[i]]);
            }
        }

        #pragma unroll
        for (int ks = 0; ks < 4; ks++) {
            const int kk = ks * 8;
            float a[4][4];
            #pragma unroll
            for (int mi = 0; mi < 4; mi++) {
                int mb = wm * 64 + mi * 16;
                a[mi][0] = As[mb + r    ][kk + cg    ];
                a[mi][1] = As[mb + r + 8][kk + cg    ];
                a[mi][2] = As[mb + r    ][kk + cg + 4];
                a[mi][3] = As[mb + r + 8][kk + cg + 4];
            }
            #pragma unroll
            for (int ni = 0; ni < 4; ni++) {
                int nb = wn * 32 + ni * 8;
                float b0 = Bs[kk + cg    ][nb + r];
                float b1 = Bs[kk + cg + 4][nb + r];
                #pragma unroll
                for (int mi = 0; mi < 4; mi++)
                    mma_tf32(acc[mi][ni], a[mi][0], a[mi][1], a[mi][2], a[mi][3], b0, b1);
            }
        }
        __syncthreads();
    }

    // epilogue
    #pragma unroll
    for (int mi = 0; mi < 4; mi++) {
        int mb = row0 + wm * 64 + mi * 16;
        #pragma unroll
        for (int ni = 0; ni < 4; ni++) {
            int col = col0 + wn * 32 + ni * 8 + 2 * cg;
            float bs0 = bias[col], bs1 = bias[col + 1];
            #pragma unroll
            for (int half = 0; half < 2; half++) {
                int row = mb + r + half * 8;
                float v0 = acc[mi][ni][2 * half]     + bs0;
                float v1 = acc[mi][ni][2 * half + 1] + bs1;
                if (relu) { v0 = fmaxf(v0, 0.0f); v1 = fmaxf(v1, 0.0f); }
                *reinterpret_cast<float2*>(&C[(size_t)row * N + col]) = make_float2(v0, v1);
            }
        }
    }
}

// ---------------- flash attention, tf32 TC, m32 warp tiles, KTILE=32 ----------
// grid: (SEQ/128, BATCH*NHEADS); 128 threads = 4 warps x 32 query rows each
// 3 CTAs/SM target: smem 69.5KB, regs capped via __launch_bounds__(128,3)
#define QTILE 128
#define KTILE 32
#define QSTR 68
#define VSTR 72
#define PSTR (KTILE + 4)   // 36
#define ATT_SMEM ((QTILE * QSTR + KTILE * QSTR + KTILE * VSTR + QTILE * PSTR) * (int)sizeof(float))

__global__ void __launch_bounds__(128, 3)
attn_tc(const float* __restrict__ Q, const float* __restrict__ K,
        const float* __restrict__ V, float* __restrict__ O)
{
    extern __shared__ float sh[];
    float* Qs = sh;                      // [128][68]
    float* Ks = Qs + QTILE * QSTR;       // [32][68]  (seq-row x d)
    float* Vs = Ks + KTILE * QSTR;       // [32][72]  (seq-row x d)
    float* Ps = Vs + KTILE * VSTR;       // [128][36] (q-row x seq)

    const int tid  = threadIdx.x;
    const int warp = tid >> 5, lane = tid & 31;
    const int r    = lane >> 2;          // 0..7
    const int cg   = lane & 3;           // 0..3
    const int wb   = warp * 32;          // warp's query-row base (m32 per warp)

    const int qt = blockIdx.x;
    const int bh = blockIdx.y;
    const int b  = bh >> 3, h = bh & 7;
    const int base = b * SEQ;
    const int q0   = base + qt * QTILE;
    const int colh = h * DK;

    // load Q tile (128 rows, scaled by 1/sqrt(dk), rounded to tf32)
    #pragma unroll
    for (int i = 0; i < 16; i++) {
        int l   = tid + i * 128;         // 0..2047 float4 slots
        int row = l >> 4;
        int c4  = (l & 15) * 4;
        float4 v = *reinterpret_cast<const float4*>(&Q[(size_t)(q0 + row) * DMODEL + colh + c4]);
        float4 w = make_float4(f2tf32(0.125f * v.x), f2tf32(0.125f * v.y),
                               f2tf32(0.125f * v.z), f2tf32(0.125f * v.w));
        *reinterpret_cast<float4*>(&Qs[row * QSTR + c4]) = w;
    }

    float o[2][8][4] = {};
    float rmax[2][2], rsum[2][2];
    #pragma unroll
    for (int mf = 0; mf < 2; mf++)
        #pragma unroll
        for (int z = 0; z < 2; z++) { rmax[mf][z] = -1e30f; rsum[mf][z] = 0.0f; }

    for (int j0 = 0; j0 < SEQ; j0 += KTILE) {
        __syncthreads();                 // prior phase reads of Ks/Vs/Ps complete
        const int kr = base + j0;
        // K/V tiles: 32 rows x 64 d = 512 float4 each
        #pragma unroll
        for (int i = 0; i < 4; i++) {
            int l   = tid + i * 128;     // 0..511 float4 slots
            int row = l >> 4;
            int c4  = (l & 15) * 4;
            float4 kv = *reinterpret_cast<const float4*>(&K[(size_t)(kr + row) * DMODEL + colh + c4]);
            float4 vv = *reinterpret_cast<const float4*>(&V[(size_t)(kr + row) * DMODEL + colh + c4]);
            *reinterpret_cast<float4*>(&Ks[row * QSTR + c4]) =
                make_float4(f2tf32(kv.x), f2tf32(kv.y), f2tf32(kv.z), f2tf32(kv.w));
            *reinterpret_cast<float4*>(&Vs[row * VSTR + c4]) =
                make_float4(f2tf32(vv.x), f2tf32(vv.y), f2tf32(vv.z), f2tf32(vv.w));
        }
        __syncthreads();

        // S = Q @ K^T : per warp m32 x n32 x k64
        float s[2][4][4] = {};
        #pragma unroll
        for (int kk8 = 0; kk8 < 8; kk8++) {
            const int kk = kk8 * 8;
            float a[2][4];
            #pragma unroll
            for (int mf = 0; mf < 2; mf++) {
                int mb = wb + mf * 16;
                a[mf][0] = Qs[(mb + r    ) * QSTR + kk + cg    ];
                a[mf][1] = Qs[(mb + r + 8) * QSTR + kk + cg    ];
                a[mf][2] = Qs[(mb + r    ) * QSTR + kk + cg + 4];
                a[mf][3] = Qs[(mb + r + 8) * QSTR + kk + cg + 4];
            }
            #pragma unroll
            for (int ni = 0; ni < 4; ni++) {
                float b0 = Ks[(ni * 8 + r) * QSTR + kk + cg    ];
                float b1 = Ks[(ni * 8 + r) * QSTR + kk + cg + 4];
                mma_tf32(s[0][ni], a[0][0], a[0][1], a[0][2], a[0][3], b0, b1);
                mma_tf32(s[1][ni], a[1][0], a[1][1], a[1][2], a[1][3], b0, b1);
            }
        }

        // online softmax (per m-frag, per row-half)
        #pragma unroll
        for (int mf = 0; mf < 2; mf++) {
            #pragma unroll
            for (int z = 0; z < 2; z++) {
                float mx = -1e30f;
                #pragma unroll
                for (int ni = 0; ni < 4; ni++)
                    mx = fmaxf(mx, fmaxf(s[mf][ni][2 * z], s[mf][ni][2 * z + 1]));
                mx = fmaxf(mx, __shfl_xor_sync(0xffffffffu, mx, 1));
                mx = fmaxf(mx, __shfl_xor_sync(0xffffffffu, mx, 2));
                float nm   = fmaxf(rmax[mf][z], mx);
                float corr = __expf(rmax[mf][z] - nm);
                rmax[mf][z] = nm;
                float ps = 0.0f;
                #pragma unroll
                for (int ni = 0; ni < 4; ni++) {
                    float e0 = __expf(s[mf][ni][2 * z]     - nm);
                    float e1 = __expf(s[mf][ni][2 * z + 1] - nm);
                    s[mf][ni][2 * z] = e0; s[mf][ni][2 * z + 1] = e1;
                    ps += e0 + e1;
                }
                ps += __shfl_xor_sync(0xffffffffu, ps, 1);
                ps += __shfl_xor_sync(0xffffffffu, ps, 2);
                rsum[mf][z] = rsum[mf][z] * corr + ps;
                #pragma unroll
                for (int ni = 0; ni < 8; ni++) {
                    o[mf][ni][2 * z]     *= corr;
                    o[mf][ni][2 * z + 1] *= corr;
                }
            }
        }

        // write P (tf32) to smem
        #pragma unroll
        for (int mf = 0; mf < 2; mf++) {
            #pragma unroll
            for (int ni = 0; ni < 4; ni++) {
                int col = ni * 8 + 2 * cg;
                #pragma unroll
                for (int z = 0; z < 2; z++) {
                    int row = wb + mf * 16 + r + z * 8;
                    *reinterpret_cast<float2*>(&Ps[row * PSTR + col]) =
                        make_float2(f2tf32(s[mf][ni][2 * z]), f2tf32(s[mf][ni][2 * z + 1]));
                }
            }
        }
        __syncwarp();   // P written/read within the same warp's rows only

        // O += P @ V : per warp m32 x n64 x k32
        #pragma unroll
        for (int kk8 = 0; kk8 < 4; kk8++) {
            const int kk = kk8 * 8;
            float a[2][4];
            #pragma unroll
            for (int mf = 0; mf < 2; mf++) {
                int mb = wb + mf * 16;
                a[mf][0] = Ps[(mb + r    ) * PSTR + kk + cg    ];
                a[mf][1] = Ps[(mb + r + 8) * PSTR + kk + cg    ];
                a[mf][2] = Ps[(mb + r    ) * PSTR + kk + cg + 4];
                a[mf][3] = Ps[(mb + r + 8) * PSTR + kk + cg + 4];
            }
            #pragma unroll
            for (int ni = 0; ni < 8; ni++) {
                float b0 = Vs[(kk + cg    ) * VSTR + ni * 8 + r];
                float b1 = Vs[(kk + cg + 4) * VSTR + ni * 8 + r];
                mma_tf32(o[0][ni], a[0][0], a[0][1], a[0][2], a[0][3], b0, b1);
                mma_tf32(o[1][ni], a[1][0], a[1][1], a[1][2], a[1][3], b0, b1);
            }
        }
    }

    // epilogue: normalize and store
    #pragma unroll
    for (int mf = 0; mf < 2; mf++) {
        #pragma unroll
        for (int z = 0; z < 2; z++) {
            float inv = 1.0f / rsum[mf][z];
            int row = q0 + wb + mf * 16 + r + z * 8;
            #pragma unroll
            for (int ni = 0; ni < 8; ni++) {
                int col = colh + ni * 8 + 2 * cg;
                *reinterpret_cast<float2*>(&O[(size_t)row * DMODEL + col]) =
                    make_float2(o[mf][ni][2 * z] * inv, o[mf][ni][2 * z + 1] * inv);
            }
        }
    }
}

// ---------------- residual add + layernorm (reference form: /(std+eps)) -------
__global__ void __launch_bounds__(128)
add_ln_kernel(const float* __restrict__ A, const float* __restrict__ Bv,
              const float* __restrict__ gamma, const float* __restrict__ beta,
              float* __restrict__ out)
{
    const int row = blockIdx.x;
    const int tid = threadIdx.x;
    __shared__ float red[4];

    const float4 a4 = reinterpret_cast<const float4*>(A  + (size_t)row * DMODEL)[tid];
    const float4 b4 = reinterpret_cast<const float4*>(Bv + (size_t)row * DMODEL)[tid];
    float x0 = a4.x + b4.x, x1 = a4.y + b4.y, x2 = a4.z + b4.z, x3 = a4.w + b4.w;

    float s = x0 + x1 + x2 + x3;
    #pragma unroll
    for (int off = 16; off; off >>= 1) s += __shfl_xor_sync(0xffffffffu, s, off);
    if ((tid & 31) == 0) red[tid >> 5] = s;
    __syncthreads();
    s = red[0] + red[1] + red[2] + red[3];
    const float mean = s * (1.0f / DMODEL);

    float d0 = x0 - mean, d1 = x1 - mean, d2 = x2 - mean, d3 = x3 - mean;
    float v = d0 * d0 + d1 * d1 + d2 * d2 + d3 * d3;
    #pragma unroll
    for (int off = 16; off; off >>= 1) v += __shfl_xor_sync(0xffffffffu, v, off);
    __syncthreads();
    if ((tid & 31) == 0) red[tid >> 5] = v;
    __syncthreads();
    v = (red[0] + red[1] + red[2] + red[3]) * (1.0f / DMODEL);

    const float inv = 1.0f / (sqrtf(v) + EPS);
    const float4 g4  = reinterpret_cast<const float4*>(gamma)[tid];
    const float4 be4 = reinterpret_cast<const float4*>(beta )[tid];
    float4 o4;
    o4.x = d0 * inv * g4.x + be4.x;
    o4.y = d1 * inv * g4.y + be4.y;
    o4.z = d2 * inv * g4.z + be4.z;
    o4.w = d3 * inv * g4.w + be4.w;
    reinterpret_cast<float4*>(out + (size_t)row * DMODEL)[tid] = o4;
}

// ---------------- host launch --------------------------------------------------
extern "C" void kernel_launch(void* const* d_in, const int* in_sizes, int n_in,
                              void* d_out, int out_size)
{
    const float* x   = (const float*)d_in[0];
    const float* Wq  = (const float*)d_in[1];
    const float* bq  = (const float*)d_in[2];
    const float* Wk  = (const float*)d_in[3];
    const float* bk  = (const float*)d_in[4];
    const float* Wv  = (const float*)d_in[5];
    const float* bv  = (const float*)d_in[6];
    const float* Wo  = (const float*)d_in[7];
    const float* bo  = (const float*)d_in[8];
    const float* W1  = (const float*)d_in[9];
    const float* b1  = (const float*)d_in[10];
    const float* W2  = (const float*)d_in[11];
    const float* b2  = (const float*)d_in[12];
    const float* g1  = (const float*)d_in[13];
    const float* be1 = (const float*)d_in[14];
    const float* g2  = (const float*)d_in[15];
    const float* be2 = (const float*)d_in[16];
    float* out = (float*)d_out;

    float *Qp, *Kp, *Vp, *AOp, *X1p, *FFHp;
    cudaGetSymbolAddress((void**)&Qp,   g_Q);
    cudaGetSymbolAddress((void**)&Kp,   g_K);
    cudaGetSymbolAddress((void**)&Vp,   g_V);
    cudaGetSymbolAddress((void**)&AOp,  g_AO);
    cudaGetSymbolAddress((void**)&X1p,  g_X1);
    cudaGetSymbolAddress((void**)&FFHp, g_FFH);

    cudaFuncSetAttribute(attn_tc, cudaFuncAttributeMaxDynamicSharedMemorySize, ATT_SMEM);

    const dim3 t256(256), t128(128);
    const dim3 gProj(DMODEL / TBN, ROWS / TBM);   // (4, 64)
    const dim3 gFF1 (DFF    / TBN, ROWS / TBM);   // (16, 64)

    // QKV projections
    gemm_tc<<<gProj, t256>>>(x, Wq, bq, Qp, ROWS, DMODEL, DMODEL, 0);
    gemm_tc<<<gProj, t256>>>(x, Wk, bk, Kp, ROWS, DMODEL, DMODEL, 0);
    gemm_tc<<<gProj, t256>>>(x, Wv, bv, Vp, ROWS, DMODEL, DMODEL, 0);

    // attention
    attn_tc<<<dim3(SEQ / QTILE, BATCH * NHEADS), t128, ATT_SMEM>>>(Qp, Kp, Vp, AOp);

    // output projection + LN1
    gemm_tc<<<gProj, t256>>>(AOp, Wo, bo, Qp, ROWS, DMODEL, DMODEL, 0);
    add_ln_kernel<<<ROWS, 128>>>(x, Qp, g1, be1, X1p);

    // FFN
    gemm_tc<<<gFF1,  t256>>>(X1p,  W1, b1, FFHp, ROWS, DFF,    DMODEL, 1);
    gemm_tc<<<gProj, t256>>>(FFHp, W2, b2, Kp,   ROWS, DMODEL, DFF,    0);

    // LN2 -> final output
    add_ln_kernel<<<ROWS, 128>>>(X1p, Kp, g2, be2, out);
}

// round 9
// speedup vs baseline: 1.0732x; 1.0732x over previous
#include <cuda_runtime.h>
#include <math.h>
#include <stdint.h>

#define BATCH   2
#define SEQ     4096
#define DMODEL  512
#define NHEADS  8
#define DK      64
#define DFF     2048
#define ROWS    (BATCH * SEQ)   // 8192
#define EPS     1e-5f

// ---------------- scratch (static device globals; no allocs allowed) ----------
__device__ float g_Q  [ROWS * DMODEL];
__device__ float g_K  [ROWS * DMODEL];
__device__ float g_V  [ROWS * DMODEL];
__device__ float g_AO [ROWS * DMODEL];
__device__ float g_X1 [ROWS * DMODEL];
__device__ float g_FFH[ROWS * DFF];

// ---------------- tf32 / async helpers ----------------------------------------
__device__ __forceinline__ float f2tf32(float x) {
    unsigned int r;
    asm("cvt.rna.tf32.f32 %0, %1;" : "=r"(r) : "f"(x));
    return __uint_as_float(r);
}

__device__ __forceinline__ void mma_tf32(float* c,
                                         float a0, float a1, float a2, float a3,
                                         float b0, float b1)
{
    asm volatile(
        "mma.sync.aligned.m16n8k8.row.col.f32.tf32.tf32.f32 "
        "{%0,%1,%2,%3}, {%4,%5,%6,%7}, {%8,%9}, {%0,%1,%2,%3};"
        : "+f"(c[0]), "+f"(c[1]), "+f"(c[2]), "+f"(c[3])
        : "r"(__float_as_uint(a0)), "r"(__float_as_uint(a1)),
          "r"(__float_as_uint(a2)), "r"(__float_as_uint(a3)),
          "r"(__float_as_uint(b0)), "r"(__float_as_uint(b1)));
}

__device__ __forceinline__ void cp_async16(unsigned int smem_addr, const void* gptr) {
    asm volatile("cp.async.cg.shared.global [%0], [%1], 16;"
                 :: "r"(smem_addr), "l"(gptr));
}
#define CP_COMMIT() asm volatile("cp.async.commit_group;")
#define CP_WAIT0()  asm volatile("cp.async.wait_group 0;")

// ---------------- tf32 tensor-core GEMM, reg-staged double buffer -------------
// block tile 128x128x32, 256 threads, warps 2(m) x 4(n), warp tile 64x32
#define TBM 128
#define TBN 128
#define TBK 32
#define ASTR (TBK + 4)    // 36  -> A-frag pattern conflict-free
#define BSTR (TBN + 8)    // 136 -> B-frag pattern conflict-free

__global__ void __launch_bounds__(256)
gemm_tc(const float* __restrict__ A, const float* __restrict__ B,
        const float* __restrict__ bias, float* __restrict__ C,
        int M, int N, int K, int relu)
{
    __shared__ float As[TBM][ASTR];
    __shared__ float Bs[TBK][BSTR];

    const int tid  = threadIdx.x;
    const int warp = tid >> 5, lane = tid & 31;
    const int wm = warp >> 2;          // 0..1
    const int wn = warp & 3;           // 0..3
    const int r    = lane >> 2;        // 0..7
    const int cg   = lane & 3;         // 0..3
    const int row0 = blockIdx.y * TBM;
    const int col0 = blockIdx.x * TBN;

    // per-thread load coords (A: 128x32 = 1024 fl4; B: 32x128 = 1024 fl4)
    int aRow[4], aCol[4], bRow[4], bCol[4];
    #pragma unroll
    for (int i = 0; i < 4; i++) {
        int l = tid + i * 256;
        aRow[i] = l >> 3;  aCol[i] = (l & 7) * 4;
        bRow[i] = l >> 5;  bCol[i] = (l & 31) * 4;
    }

    float4 ra[4], rb[4];
    #pragma unroll
    for (int i = 0; i < 4; i++) {
        ra[i] = *reinterpret_cast<const float4*>(&A[(size_t)(row0 + aRow[i]) * K + aCol[i]]);
        rb[i] = *reinterpret_cast<const float4*>(&B[(size_t)bRow[i] * N + col0 + bCol[i]]);
    }

    float acc[4][4][4] = {};           // [mfrag][nfrag][c0..c3]

    for (int k0 = 0; k0 < K; k0 += TBK) {
        // commit staged tile to smem (tf32-rounded)
        #pragma unroll
        for (int i = 0; i < 4; i++) {
            *reinterpret_cast<float4*>(&As[aRow[i]][aCol[i]]) =
                make_float4(f2tf32(ra[i].x), f2tf32(ra[i].y), f2tf32(ra[i].z), f2tf32(ra[i].w));
            *reinterpret_cast<float4*>(&Bs[bRow[i]][bCol[i]]) =
                make_float4(f2tf32(rb[i].x), f2tf32(rb[i].y), f2tf32(rb[i].z), f2tf32(rb[i].w));
        }
        __syncthreads();

        // prefetch next tile into registers (overlaps MMA below)
        if (k0 + TBK < K) {
            #pragma unroll
            for (int i = 0; i < 4; i++) {
                ra[i] = *reinterpret_cast<const float4*>(
                    &A[(size_t)(row0 + aRow[i]) * K + k0 + TBK + aCol[i]]);
                rb[i] = *reinterpret_cast<const float4*>(
                    &B[(size_t)(k0 + TBK + bRow[i]) * N + col0 + bCol[i]]);
            }
        }

        #pragma unroll
        for (int ks = 0; ks < 4; ks++) {
            const int kk = ks * 8;
            float a[4][4];
            #pragma unroll
            for (int mi = 0; mi < 4; mi++) {
                int mb = wm * 64 + mi * 16;
                a[mi][0] = As[mb + r    ][kk + cg    ];
                a[mi][1] = As[mb + r + 8][kk + cg    ];
                a[mi][2] = As[mb + r    ][kk + cg + 4];
                a[mi][3] = As[mb + r + 8][kk + cg + 4];
            }
            #pragma unroll
            for (int ni = 0; ni < 4; ni++) {
                int nb = wn * 32 + ni * 8;
                float b0 = Bs[kk + cg    ][nb + r];
                float b1 = Bs[kk + cg + 4][nb + r];
                #pragma unroll
                for (int mi = 0; mi < 4; mi++)
                    mma_tf32(acc[mi][ni], a[mi][0], a[mi][1], a[mi][2], a[mi][3], b0, b1);
            }
        }
        __syncthreads();
    }

    // epilogue
    #pragma unroll
    for (int mi = 0; mi < 4; mi++) {
        int mb = row0 + wm * 64 + mi * 16;
        #pragma unroll
        for (int ni = 0; ni < 4; ni++) {
            int col = col0 + wn * 32 + ni * 8 + 2 * cg;
            float bs0 = bias[col], bs1 = bias[col + 1];
            #pragma unroll
            for (int half = 0; half < 2; half++) {
                int row = mb + r + half * 8;
                float v0 = acc[mi][ni][2 * half]     + bs0;
                float v1 = acc[mi][ni][2 * half + 1] + bs1;
                if (relu) { v0 = fmaxf(v0, 0.0f); v1 = fmaxf(v1, 0.0f); }
                *reinterpret_cast<float2*>(&C[(size_t)row * N + col]) = make_float2(v0, v1);
            }
        }
    }
}

// ---------------- flash attention, tf32 TC, m32 warp tiles, cp.async overlap --
// grid: (SEQ/128, BATCH*NHEADS); 128 threads = 4 warps x 32 query rows each
// K(j+1) prefetched during PV(j); V(j) prefetched during S(j). Single buffer.
// NOTE: K/V tiles are 64 rows x 16 float4 = 1024 slots -> 8 float4 PER THREAD.
#define QTILE 128
#define KTILE 64
#define QSTR 68
#define VSTR 72
#define ATT_SMEM ((QTILE * QSTR + KTILE * QSTR + KTILE * VSTR + QTILE * QSTR) * (int)sizeof(float))

__global__ void __launch_bounds__(128)
attn_tc(const float* __restrict__ Q, const float* __restrict__ K,
        const float* __restrict__ V, float* __restrict__ O)
{
    extern __shared__ float sh[];
    float* Qs = sh;                      // [128][68]
    float* Ks = Qs + QTILE * QSTR;       // [64][68]
    float* Vs = Ks + KTILE * QSTR;       // [64][72]
    float* Ps = Vs + KTILE * VSTR;       // [128][68]

    const int tid  = threadIdx.x;
    const int warp = tid >> 5, lane = tid & 31;
    const int r    = lane >> 2;          // 0..7
    const int cg   = lane & 3;           // 0..3
    const int wb   = warp * 32;          // warp's query-row base (m32 per warp)

    const int qt = blockIdx.x;
    const int bh = blockIdx.y;
    const int b  = bh >> 3, h = bh & 7;
    const int base = b * SEQ;
    const int q0   = base + qt * QTILE;
    const int colh = h * DK;

    // per-thread K/V copy coords: 64 rows x 64 d = 1024 float4, 8 per thread
    int kvRow[8], kvC4[8];
    unsigned int ksAddr[8], vsAddr[8];
    #pragma unroll
    for (int i = 0; i < 8; i++) {
        int l = tid + i * 128;           // 0..1023
        kvRow[i] = l >> 4;               // 0..63
        kvC4[i]  = (l & 15) * 4;         // 0..60
        ksAddr[i] = (unsigned int)__cvta_generic_to_shared(&Ks[kvRow[i] * QSTR + kvC4[i]]);
        vsAddr[i] = (unsigned int)__cvta_generic_to_shared(&Vs[kvRow[i] * VSTR + kvC4[i]]);
    }

    // prologue: start K(0) load, then stage Q (scaled, tf32-rounded)
    #pragma unroll
    for (int i = 0; i < 8; i++)
        cp_async16(ksAddr[i], &K[(size_t)(base + kvRow[i]) * DMODEL + colh + kvC4[i]]);
    CP_COMMIT();

    #pragma unroll
    for (int i = 0; i < 16; i++) {
        int l   = tid + i * 128;         // 0..2047 float4 slots
        int row = l >> 4;
        int c4  = (l & 15) * 4;
        float4 v = *reinterpret_cast<const float4*>(&Q[(size_t)(q0 + row) * DMODEL + colh + c4]);
        float4 w = make_float4(f2tf32(0.125f * v.x), f2tf32(0.125f * v.y),
                               f2tf32(0.125f * v.z), f2tf32(0.125f * v.w));
        *reinterpret_cast<float4*>(&Qs[row * QSTR + c4]) = w;
    }

    float o[2][8][4] = {};
    float rmax[2][2], rsum[2][2];
    #pragma unroll
    for (int mf = 0; mf < 2; mf++)
        #pragma unroll
        for (int z = 0; z < 2; z++) { rmax[mf][z] = -1e30f; rsum[mf][z] = 0.0f; }

    for (int j0 = 0; j0 < SEQ; j0 += KTILE) {
        const int kr = base + j0;

        CP_WAIT0();
        __syncthreads();                 // Ks(j) ready; everyone past PV(j-1)

        // overlap: start V(j) load (Vs free — PV(j-1) done)
        #pragma unroll
        for (int i = 0; i < 8; i++)
            cp_async16(vsAddr[i], &V[(size_t)(kr + kvRow[i]) * DMODEL + colh + kvC4[i]]);
        CP_COMMIT();

        // S = Q @ K^T : per warp m32 x n64 x k64
        float s[2][8][4] = {};
        #pragma unroll
        for (int kk8 = 0; kk8 < 8; kk8++) {
            const int kk = kk8 * 8;
            float a[2][4];
            #pragma unroll
            for (int mf = 0; mf < 2; mf++) {
                int mb = wb + mf * 16;
                a[mf][0] = Qs[(mb + r    ) * QSTR + kk + cg    ];
                a[mf][1] = Qs[(mb + r + 8) * QSTR + kk + cg    ];
                a[mf][2] = Qs[(mb + r    ) * QSTR + kk + cg + 4];
                a[mf][3] = Qs[(mb + r + 8) * QSTR + kk + cg + 4];
            }
            #pragma unroll
            for (int ni = 0; ni < 8; ni++) {
                float b0 = Ks[(ni * 8 + r) * QSTR + kk + cg    ];
                float b1 = Ks[(ni * 8 + r) * QSTR + kk + cg + 4];
                mma_tf32(s[0][ni], a[0][0], a[0][1], a[0][2], a[0][3], b0, b1);
                mma_tf32(s[1][ni], a[1][0], a[1][1], a[1][2], a[1][3], b0, b1);
            }
        }

        CP_WAIT0();
        __syncthreads();                 // Vs(j) ready; all warps done reading Ks(j)

        // online softmax (per m-frag, per row-half)
        #pragma unroll
        for (int mf = 0; mf < 2; mf++) {
            #pragma unroll
            for (int z = 0; z < 2; z++) {
                float mx = -1e30f;
                #pragma unroll
                for (int ni = 0; ni < 8; ni++)
                    mx = fmaxf(mx, fmaxf(s[mf][ni][2 * z], s[mf][ni][2 * z + 1]));
                mx = fmaxf(mx, __shfl_xor_sync(0xffffffffu, mx, 1));
                mx = fmaxf(mx, __shfl_xor_sync(0xffffffffu, mx, 2));
                float nm   = fmaxf(rmax[mf][z], mx);
                float corr = __expf(rmax[mf][z] - nm);
                rmax[mf][z] = nm;
                float ps = 0.0f;
                #pragma unroll
                for (int ni = 0; ni < 8; ni++) {
                    float e0 = __expf(s[mf][ni][2 * z]     - nm);
                    float e1 = __expf(s[mf][ni][2 * z + 1] - nm);
                    s[mf][ni][2 * z] = e0; s[mf][ni][2 * z + 1] = e1;
                    ps += e0 + e1;
                }
                ps += __shfl_xor_sync(0xffffffffu, ps, 1);
                ps += __shfl_xor_sync(0xffffffffu, ps, 2);
                rsum[mf][z] = rsum[mf][z] * corr + ps;
                #pragma unroll
                for (int ni = 0; ni < 8; ni++) {
                    o[mf][ni][2 * z]     *= corr;
                    o[mf][ni][2 * z + 1] *= corr;
                }
            }
        }

        // write P (tf32) to smem
        #pragma unroll
        for (int mf = 0; mf < 2; mf++) {
            #pragma unroll
            for (int ni = 0; ni < 8; ni++) {
                int col = ni * 8 + 2 * cg;
                #pragma unroll
                for (int z = 0; z < 2; z++) {
                    int row = wb + mf * 16 + r + z * 8;
                    *reinterpret_cast<float2*>(&Ps[row * QSTR + col]) =
                        make_float2(f2tf32(s[mf][ni][2 * z]), f2tf32(s[mf][ni][2 * z + 1]));
                }
            }
        }
        __syncwarp();   // P written/read within the same warp's rows only

        // overlap: start K(j+1) load (Ks free — S(j) done CTA-wide at last barrier)
        if (j0 + KTILE < SEQ) {
            #pragma unroll
            for (int i = 0; i < 8; i++)
                cp_async16(ksAddr[i], &K[(size_t)(kr + KTILE + kvRow[i]) * DMODEL + colh + kvC4[i]]);
            CP_COMMIT();
        }

        // O += P @ V : per warp m32 x n64 x k64
        #pragma unroll
        for (int kk8 = 0; kk8 < 8; kk8++) {
            const int kk = kk8 * 8;
            float a[2][4];
            #pragma unroll
            for (int mf = 0; mf < 2; mf++) {
                int mb = wb + mf * 16;
                a[mf][0] = Ps[(mb + r    ) * QSTR + kk + cg    ];
                a[mf][1] = Ps[(mb + r + 8) * QSTR + kk + cg    ];
                a[mf][2] = Ps[(mb + r    ) * QSTR + kk + cg + 4];
                a[mf][3] = Ps[(mb + r + 8) * QSTR + kk + cg + 4];
            }
            #pragma unroll
            for (int ni = 0; ni < 8; ni++) {
                float b0 = Vs[(kk + cg    ) * VSTR + ni * 8 + r];
                float b1 = Vs[(kk + cg + 4) * VSTR + ni * 8 + r];
                mma_tf32(o[0][ni], a[0][0], a[0][1], a[0][2], a[0][3], b0, b1);
                mma_tf32(o[1][ni], a[1][0], a[1][1], a[1][2], a[1][3], b0, b1);
            }
        }
    }

    // epilogue: normalize and store
    #pragma unroll
    for (int mf = 0; mf < 2; mf++) {
        #pragma unroll
        for (int z = 0; z < 2; z++) {
            float inv = 1.0f / rsum[mf][z];
            int row = q0 + wb + mf * 16 + r + z * 8;
            #pragma unroll
            for (int ni = 0; ni < 8; ni++) {
                int col = colh + ni * 8 + 2 * cg;
                *reinterpret_cast<float2*>(&O[(size_t)row * DMODEL + col]) =
                    make_float2(o[mf][ni][2 * z] * inv, o[mf][ni][2 * z + 1] * inv);
            }
        }
    }
}

// ---------------- residual add + layernorm (reference form: /(std+eps)) -------
__global__ void __launch_bounds__(128)
add_ln_kernel(const float* __restrict__ A, const float* __restrict__ Bv,
              const float* __restrict__ gamma, const float* __restrict__ beta,
              float* __restrict__ out)
{
    const int row = blockIdx.x;
    const int tid = threadIdx.x;
    __shared__ float red[4];

    const float4 a4 = reinterpret_cast<const float4*>(A  + (size_t)row * DMODEL)[tid];
    const float4 b4 = reinterpret_cast<const float4*>(Bv + (size_t)row * DMODEL)[tid];
    float x0 = a4.x + b4.x, x1 = a4.y + b4.y, x2 = a4.z + b4.z, x3 = a4.w + b4.w;

    float s = x0 + x1 + x2 + x3;
    #pragma unroll
    for (int off = 16; off; off >>= 1) s += __shfl_xor_sync(0xffffffffu, s, off);
    if ((tid & 31) == 0) red[tid >> 5] = s;
    __syncthreads();
    s = red[0] + red[1] + red[2] + red[3];
    const float mean = s * (1.0f / DMODEL);

    float d0 = x0 - mean, d1 = x1 - mean, d2 = x2 - mean, d3 = x3 - mean;
    float v = d0 * d0 + d1 * d1 + d2 * d2 + d3 * d3;
    #pragma unroll
    for (int off = 16; off; off >>= 1) v += __shfl_xor_sync(0xffffffffu, v, off);
    __syncthreads();
    if ((tid & 31) == 0) red[tid >> 5] = v;
    __syncthreads();
    v = (red[0] + red[1] + red[2] + red[3]) * (1.0f / DMODEL);

    const float inv = 1.0f / (sqrtf(v) + EPS);
    const float4 g4  = reinterpret_cast<const float4*>(gamma)[tid];
    const float4 be4 = reinterpret_cast<const float4*>(beta )[tid];
    float4 o4;
    o4.x = d0 * inv * g4.x + be4.x;
    o4.y = d1 * inv * g4.y + be4.y;
    o4.z = d2 * inv * g4.z + be4.z;
    o4.w = d3 * inv * g4.w + be4.w;
    reinterpret_cast<float4*>(out + (size_t)row * DMODEL)[tid] = o4;
}

// ---------------- host launch --------------------------------------------------
extern "C" void kernel_launch(void* const* d_in, const int* in_sizes, int n_in,
                              void* d_out, int out_size)
{
    const float* x   = (const float*)d_in[0];
    const float* Wq  = (const float*)d_in[1];
    const float* bq  = (const float*)d_in[2];
    const float* Wk  = (const float*)d_in[3];
    const float* bk  = (const float*)d_in[4];
    const float* Wv  = (const float*)d_in[5];
    const float* bv  = (const float*)d_in[6];
    const float* Wo  = (const float*)d_in[7];
    const float* bo  = (const float*)d_in[8];
    const float* W1  = (const float*)d_in[9];
    const float* b1  = (const float*)d_in[10];
    const float* W2  = (const float*)d_in[11];
    const float* b2  = (const float*)d_in[12];
    const float* g1  = (const float*)d_in[13];
    const float* be1 = (const float*)d_in[14];
    const float* g2  = (const float*)d_in[15];
    const float* be2 = (const float*)d_in[16];
    float* out = (float*)d_out;

    float *Qp, *Kp, *Vp, *AOp, *X1p, *FFHp;
    cudaGetSymbolAddress((void**)&Qp,   g_Q);
    cudaGetSymbolAddress((void**)&Kp,   g_K);
    cudaGetSymbolAddress((void**)&Vp,   g_V);
    cudaGetSymbolAddress((void**)&AOp,  g_AO);
    cudaGetSymbolAddress((void**)&X1p,  g_X1);
    cudaGetSymbolAddress((void**)&FFHp, g_FFH);

    cudaFuncSetAttribute(attn_tc, cudaFuncAttributeMaxDynamicSharedMemorySize, ATT_SMEM);

    const dim3 t256(256), t128(128);
    const dim3 gProj(DMODEL / TBN, ROWS / TBM);   // (4, 64)
    const dim3 gFF1 (DFF    / TBN, ROWS / TBM);   // (16, 64)

    // QKV projections
    gemm_tc<<<gProj, t256>>>(x, Wq, bq, Qp, ROWS, DMODEL, DMODEL, 0);
    gemm_tc<<<gProj, t256>>>(x, Wk, bk, Kp, ROWS, DMODEL, DMODEL, 0);
    gemm_tc<<<gProj, t256>>>(x, Wv, bv, Vp, ROWS, DMODEL, DMODEL, 0);

    // attention
    attn_tc<<<dim3(SEQ / QTILE, BATCH * NHEADS), t128, ATT_SMEM>>>(Qp, Kp, Vp, AOp);

    // output projection + LN1
    gemm_tc<<<gProj, t256>>>(AOp, Wo, bo, Qp, ROWS, DMODEL, DMODEL, 0);
    add_ln_kernel<<<ROWS, 128>>>(x, Qp, g1, be1, X1p);

    // FFN
    gemm_tc<<<gFF1,  t256>>>(X1p,  W1, b1, FFHp, ROWS, DFF,    DMODEL, 1);
    gemm_tc<<<gProj, t256>>>(FFHp, W2, b2, Kp,   ROWS, DMODEL, DFF,    0);

    // LN2 -> final output
    add_ln_kernel<<<ROWS, 128>>>(X1p, Kp, g2, be2, out);
}

// round 10
// speedup vs baseline: 1.2065x; 1.1242x over previous
#include <cuda_runtime.h>
#include <math.h>
#include <stdint.h>

#define BATCH   2
#define SEQ     4096
#define DMODEL  512
#define NHEADS  8
#define DK      64
#define DFF     2048
#define ROWS    (BATCH * SEQ)   // 8192
#define EPS     1e-5f

// ---------------- scratch (static device globals; no allocs allowed) ----------
__device__ float g_Q  [ROWS * DMODEL];
__device__ float g_K  [ROWS * DMODEL];
__device__ float g_V  [ROWS * DMODEL];
__device__ float g_AO [ROWS * DMODEL];
__device__ float g_X1 [ROWS * DMODEL];
__device__ float g_FFH[ROWS * DFF];

// ---------------- tf32 / async helpers ----------------------------------------
__device__ __forceinline__ float f2tf32(float x) {
    unsigned int r;
    asm("cvt.rna.tf32.f32 %0, %1;" : "=r"(r) : "f"(x));
    return __uint_as_float(r);
}

__device__ __forceinline__ float fex2(float x) {   // 2^x via MUFU.EX2
    float y;
    asm("ex2.approx.f32 %0, %1;" : "=f"(y) : "f"(x));
    return y;
}

__device__ __forceinline__ void mma_tf32(float* c,
                                         float a0, float a1, float a2, float a3,
                                         float b0, float b1)
{
    asm volatile(
        "mma.sync.aligned.m16n8k8.row.col.f32.tf32.tf32.f32 "
        "{%0,%1,%2,%3}, {%4,%5,%6,%7}, {%8,%9}, {%0,%1,%2,%3};"
        : "+f"(c[0]), "+f"(c[1]), "+f"(c[2]), "+f"(c[3])
        : "r"(__float_as_uint(a0)), "r"(__float_as_uint(a1)),
          "r"(__float_as_uint(a2)), "r"(__float_as_uint(a3)),
          "r"(__float_as_uint(b0)), "r"(__float_as_uint(b1)));
}

__device__ __forceinline__ void cp_async16(unsigned int smem_addr, const void* gptr) {
    asm volatile("cp.async.cg.shared.global [%0], [%1], 16;"
                 :: "r"(smem_addr), "l"(gptr));
}
#define CP_COMMIT() asm volatile("cp.async.commit_group;")
#define CP_WAIT0()  asm volatile("cp.async.wait_group 0;")
#define CP_WAIT1()  asm volatile("cp.async.wait_group 1;")

// ---------------- tf32 tensor-core GEMM, 3-stage cp.async pipeline ------------
// block tile 128x128x32, 256 threads, warps 2(m) x 4(n), warp tile 64x32
#define TBM 128
#define TBN 128
#define TBK 32
#define ASTR (TBK + 4)    // 36  -> A-frag pattern conflict-free
#define BSTR (TBN + 8)    // 136 -> B-frag pattern conflict-free
#define NSTG 3
#define STGF (TBM * ASTR + TBK * BSTR)            // floats per stage = 8960
#define GEMM_SMEM (NSTG * STGF * (int)sizeof(float))  // 107520 bytes

__device__ __forceinline__ void gemm_body(
    const float* __restrict__ A, const float* __restrict__ B,
    const float* __restrict__ bias, float* __restrict__ C,
    int N, int K, int relu, int row0, int col0)
{
    extern __shared__ float gsm[];

    const int tid  = threadIdx.x;
    const int warp = tid >> 5, lane = tid & 31;
    const int wm = warp >> 2;          // 0..1
    const int wn = warp & 3;           // 0..3
    const int r    = lane >> 2;        // 0..7
    const int cg   = lane & 3;         // 0..3

    // per-thread chunk coords (A: 128x32 = 1024 fl4; B: 32x128 = 1024 fl4; 4 each)
    int aRow[4], aCol[4], bRow[4], bCol[4];
    unsigned int aOffB[4], bOffB[4];   // byte offsets within one stage
    #pragma unroll
    for (int i = 0; i < 4; i++) {
        int l = tid + i * 256;
        aRow[i] = l >> 3;  aCol[i] = (l & 7) * 4;
        bRow[i] = l >> 5;  bCol[i] = (l & 31) * 4;
        aOffB[i] = (unsigned int)(aRow[i] * ASTR + aCol[i]) * 4u;
        bOffB[i] = (unsigned int)(TBM * ASTR + bRow[i] * BSTR + bCol[i]) * 4u;
    }
    const unsigned int smemBase = (unsigned int)__cvta_generic_to_shared(gsm);

    auto issue = [&](int stg, int k0) {
        unsigned int sb = smemBase + (unsigned int)(stg * STGF) * 4u;
        #pragma unroll
        for (int i = 0; i < 4; i++) {
            cp_async16(sb + aOffB[i], &A[(size_t)(row0 + aRow[i]) * K + k0 + aCol[i]]);
            cp_async16(sb + bOffB[i], &B[(size_t)(k0 + bRow[i]) * N + col0 + bCol[i]]);
        }
        CP_COMMIT();
    };

    float acc[4][4][4] = {};           // [mfrag][nfrag][c0..c3]

    const int NT = K / TBK;
    issue(0, 0);

    for (int kt = 0; kt < NT; kt++) {
        const int cur = kt % NSTG;
        if (kt + 1 < NT) { issue((kt + 1) % NSTG, (kt + 1) * TBK); CP_WAIT1(); }
        else             { CP_WAIT0(); }
        __syncthreads();

        const float* As_ = gsm + cur * STGF;
        const float* Bs_ = As_ + TBM * ASTR;

        #pragma unroll
        for (int ks = 0; ks < 4; ks++) {
            const int kk = ks * 8;
            float a[4][4];
            #pragma unroll
            for (int mi = 0; mi < 4; mi++) {
                int mb = wm * 64 + mi * 16;
                a[mi][0] = As_[(mb + r    ) * ASTR + kk + cg    ];
                a[mi][1] = As_[(mb + r + 8) * ASTR + kk + cg    ];
                a[mi][2] = As_[(mb + r    ) * ASTR + kk + cg + 4];
                a[mi][3] = As_[(mb + r + 8) * ASTR + kk + cg + 4];
            }
            #pragma unroll
            for (int ni = 0; ni < 4; ni++) {
                int nb = wn * 32 + ni * 8;
                float b0 = Bs_[(kk + cg    ) * BSTR + nb + r];
                float b1 = Bs_[(kk + cg + 4) * BSTR + nb + r];
                #pragma unroll
                for (int mi = 0; mi < 4; mi++)
                    mma_tf32(acc[mi][ni], a[mi][0], a[mi][1], a[mi][2], a[mi][3], b0, b1);
            }
        }
    }

    // epilogue
    #pragma unroll
    for (int mi = 0; mi < 4; mi++) {
        int mb = row0 + wm * 64 + mi * 16;
        #pragma unroll
        for (int ni = 0; ni < 4; ni++) {
            int col = col0 + wn * 32 + ni * 8 + 2 * cg;
            float bs0 = bias[col], bs1 = bias[col + 1];
            #pragma unroll
            for (int half = 0; half < 2; half++) {
                int row = mb + r + half * 8;
                float v0 = acc[mi][ni][2 * half]     + bs0;
                float v1 = acc[mi][ni][2 * half + 1] + bs1;
                if (relu) { v0 = fmaxf(v0, 0.0f); v1 = fmaxf(v1, 0.0f); }
                *reinterpret_cast<float2*>(&C[(size_t)row * N + col]) = make_float2(v0, v1);
            }
        }
    }
}

__global__ void __launch_bounds__(256)
gemm_tc(const float* __restrict__ A, const float* __restrict__ B,
        const float* __restrict__ bias, float* __restrict__ C,
        int N, int K, int relu)
{
    gemm_body(A, B, bias, C, N, K, relu, blockIdx.y * TBM, blockIdx.x * TBN);
}

// fused QKV: grid.z in {0,1,2} selects projection
__global__ void __launch_bounds__(256)
qkv_tc(const float* __restrict__ x,
       const float* __restrict__ Wq, const float* __restrict__ Wk, const float* __restrict__ Wv,
       const float* __restrict__ bq, const float* __restrict__ bk, const float* __restrict__ bv,
       float* __restrict__ Qo, float* __restrict__ Ko, float* __restrict__ Vo)
{
    const float* W = (blockIdx.z == 0) ? Wq : (blockIdx.z == 1) ? Wk : Wv;
    const float* bb = (blockIdx.z == 0) ? bq : (blockIdx.z == 1) ? bk : bv;
    float*       O = (blockIdx.z == 0) ? Qo : (blockIdx.z == 1) ? Ko : Vo;
    gemm_body(x, W, bb, O, DMODEL, DMODEL, 0, blockIdx.y * TBM, blockIdx.x * TBN);
}

// ---------------- flash attention, tf32 TC, m32 warp tiles, cp.async overlap --
// grid: (SEQ/128, BATCH*NHEADS); 128 threads = 4 warps x 32 query rows each
// V(j) prefetched during S(j)+softmax(j); K(j+1) prefetched during PV(j).
// Scores computed in log2 domain (Q pre-scaled by 1/sqrt(dk)*log2(e)); exp = MUFU.EX2.
#define QTILE 128
#define KTILE 64
#define QSTR 68
#define VSTR 72
#define ATT_SMEM ((QTILE * QSTR + KTILE * QSTR + KTILE * VSTR + QTILE * QSTR) * (int)sizeof(float))
#define QSCALE 0.18033688011f   // 0.125 * log2(e)

__global__ void __launch_bounds__(128)
attn_tc(const float* __restrict__ Q, const float* __restrict__ K,
        const float* __restrict__ V, float* __restrict__ O)
{
    extern __shared__ float sh[];
    float* Qs = sh;                      // [128][68]
    float* Ks = Qs + QTILE * QSTR;       // [64][68]
    float* Vs = Ks + KTILE * QSTR;       // [64][72]
    float* Ps = Vs + KTILE * VSTR;       // [128][68]

    const int tid  = threadIdx.x;
    const int warp = tid >> 5, lane = tid & 31;
    const int r    = lane >> 2;          // 0..7
    const int cg   = lane & 3;           // 0..3
    const int wb   = warp * 32;          // warp's query-row base (m32 per warp)

    const int qt = blockIdx.x;
    const int bh = blockIdx.y;
    const int b  = bh >> 3, h = bh & 7;
    const int base = b * SEQ;
    const int q0   = base + qt * QTILE;
    const int colh = h * DK;

    // per-thread K/V copy coords: 64 rows x 64 d = 1024 float4, 8 per thread
    int kvRow[8], kvC4[8];
    unsigned int ksAddr[8], vsAddr[8];
    #pragma unroll
    for (int i = 0; i < 8; i++) {
        int l = tid + i * 128;           // 0..1023
        kvRow[i] = l >> 4;               // 0..63
        kvC4[i]  = (l & 15) * 4;         // 0..60
        ksAddr[i] = (unsigned int)__cvta_generic_to_shared(&Ks[kvRow[i] * QSTR + kvC4[i]]);
        vsAddr[i] = (unsigned int)__cvta_generic_to_shared(&Vs[kvRow[i] * VSTR + kvC4[i]]);
    }

    // prologue: start K(0) load, then stage Q (scaled into log2 domain, tf32-rounded)
    #pragma unroll
    for (int i = 0; i < 8; i++)
        cp_async16(ksAddr[i], &K[(size_t)(base + kvRow[i]) * DMODEL + colh + kvC4[i]]);
    CP_COMMIT();

    #pragma unroll
    for (int i = 0; i < 16; i++) {
        int l   = tid + i * 128;         // 0..2047 float4 slots
        int row = l >> 4;
        int c4  = (l & 15) * 4;
        float4 v = *reinterpret_cast<const float4*>(&Q[(size_t)(q0 + row) * DMODEL + colh + c4]);
        float4 w = make_float4(f2tf32(QSCALE * v.x), f2tf32(QSCALE * v.y),
                               f2tf32(QSCALE * v.z), f2tf32(QSCALE * v.w));
        *reinterpret_cast<float4*>(&Qs[row * QSTR + c4]) = w;
    }

    float o[2][8][4] = {};
    float rmax[2][2], rsum[2][2];
    #pragma unroll
    for (int mf = 0; mf < 2; mf++)
        #pragma unroll
        for (int z = 0; z < 2; z++) { rmax[mf][z] = -1e30f; rsum[mf][z] = 0.0f; }

    for (int j0 = 0; j0 < SEQ; j0 += KTILE) {
        const int kr = base + j0;

        CP_WAIT0();
        __syncthreads();                 // Ks(j) ready; everyone past PV(j-1)

        // overlap: start V(j) load (Vs free — PV(j-1) done)
        #pragma unroll
        for (int i = 0; i < 8; i++)
            cp_async16(vsAddr[i], &V[(size_t)(kr + kvRow[i]) * DMODEL + colh + kvC4[i]]);
        CP_COMMIT();

        // S = Q @ K^T : per warp m32 x n64 x k64 (log2-domain scores)
        float s[2][8][4] = {};
        #pragma unroll
        for (int kk8 = 0; kk8 < 8; kk8++) {
            const int kk = kk8 * 8;
            float a[2][4];
            #pragma unroll
            for (int mf = 0; mf < 2; mf++) {
                int mb = wb + mf * 16;
                a[mf][0] = Qs[(mb + r    ) * QSTR + kk + cg    ];
                a[mf][1] = Qs[(mb + r + 8) * QSTR + kk + cg    ];
                a[mf][2] = Qs[(mb + r    ) * QSTR + kk + cg + 4];
                a[mf][3] = Qs[(mb + r + 8) * QSTR + kk + cg + 4];
            }
            #pragma unroll
            for (int ni = 0; ni < 8; ni++) {
                float b0 = Ks[(ni * 8 + r) * QSTR + kk + cg    ];
                float b1 = Ks[(ni * 8 + r) * QSTR + kk + cg + 4];
                mma_tf32(s[0][ni], a[0][0], a[0][1], a[0][2], a[0][3], b0, b1);
                mma_tf32(s[1][ni], a[1][0], a[1][1], a[1][2], a[1][3], b0, b1);
            }
        }

        // online softmax (register-local; overlaps with V(j) DMA in flight)
        #pragma unroll
        for (int mf = 0; mf < 2; mf++) {
            #pragma unroll
            for (int z = 0; z < 2; z++) {
                float mx = -1e30f;
                #pragma unroll
                for (int ni = 0; ni < 8; ni++)
                    mx = fmaxf(mx, fmaxf(s[mf][ni][2 * z], s[mf][ni][2 * z + 1]));
                mx = fmaxf(mx, __shfl_xor_sync(0xffffffffu, mx, 1));
                mx = fmaxf(mx, __shfl_xor_sync(0xffffffffu, mx, 2));
                float nm   = fmaxf(rmax[mf][z], mx);
                float corr = fex2(rmax[mf][z] - nm);
                rmax[mf][z] = nm;
                float ps = 0.0f;
                #pragma unroll
                for (int ni = 0; ni < 8; ni++) {
                    float e0 = fex2(s[mf][ni][2 * z]     - nm);
                    float e1 = fex2(s[mf][ni][2 * z + 1] - nm);
                    s[mf][ni][2 * z] = e0; s[mf][ni][2 * z + 1] = e1;
                    ps += e0 + e1;
                }
                ps += __shfl_xor_sync(0xffffffffu, ps, 1);
                ps += __shfl_xor_sync(0xffffffffu, ps, 2);
                rsum[mf][z] = rsum[mf][z] * corr + ps;
                #pragma unroll
                for (int ni = 0; ni < 8; ni++) {
                    o[mf][ni][2 * z]     *= corr;
                    o[mf][ni][2 * z + 1] *= corr;
                }
            }
        }

        CP_WAIT0();
        __syncthreads();                 // Vs(j) ready; all warps done reading Ks(j)

        // write P (tf32) to smem
        #pragma unroll
        for (int mf = 0; mf < 2; mf++) {
            #pragma unroll
            for (int ni = 0; ni < 8; ni++) {
                int col = ni * 8 + 2 * cg;
                #pragma unroll
                for (int z = 0; z < 2; z++) {
                    int row = wb + mf * 16 + r + z * 8;
                    *reinterpret_cast<float2*>(&Ps[row * QSTR + col]) =
                        make_float2(f2tf32(s[mf][ni][2 * z]), f2tf32(s[mf][ni][2 * z + 1]));
                }
            }
        }
        __syncwarp();   // P written/read within the same warp's rows only

        // overlap: start K(j+1) load (Ks free — S(j) done CTA-wide at last barrier)
        if (j0 + KTILE < SEQ) {
            #pragma unroll
            for (int i = 0; i < 8; i++)
                cp_async16(ksAddr[i], &K[(size_t)(kr + KTILE + kvRow[i]) * DMODEL + colh + kvC4[i]]);
            CP_COMMIT();
        }

        // O += P @ V : per warp m32 x n64 x k64
        #pragma unroll
        for (int kk8 = 0; kk8 < 8; kk8++) {
            const int kk = kk8 * 8;
            float a[2][4];
            #pragma unroll
            for (int mf = 0; mf < 2; mf++) {
                int mb = wb + mf * 16;
                a[mf][0] = Ps[(mb + r    ) * QSTR + kk + cg    ];
                a[mf][1] = Ps[(mb + r + 8) * QSTR + kk + cg    ];
                a[mf][2] = Ps[(mb + r    ) * QSTR + kk + cg + 4];
                a[mf][3] = Ps[(mb + r + 8) * QSTR + kk + cg + 4];
            }
            #pragma unroll
            for (int ni = 0; ni < 8; ni++) {
                float b0 = Vs[(kk + cg    ) * VSTR + ni * 8 + r];
                float b1 = Vs[(kk + cg + 4) * VSTR + ni * 8 + r];
                mma_tf32(o[0][ni], a[0][0], a[0][1], a[0][2], a[0][3], b0, b1);
                mma_tf32(o[1][ni], a[1][0], a[1][1], a[1][2], a[1][3], b0, b1);
            }
        }
    }

    // epilogue: normalize and store
    #pragma unroll
    for (int mf = 0; mf < 2; mf++) {
        #pragma unroll
        for (int z = 0; z < 2; z++) {
            float inv = 1.0f / rsum[mf][z];
            int row = q0 + wb + mf * 16 + r + z * 8;
            #pragma unroll
            for (int ni = 0; ni < 8; ni++) {
                int col = colh + ni * 8 + 2 * cg;
                *reinterpret_cast<float2*>(&O[(size_t)row * DMODEL + col]) =
                    make_float2(o[mf][ni][2 * z] * inv, o[mf][ni][2 * z + 1] * inv);
            }
        }
    }
}

// ---------------- residual add + layernorm (reference form: /(std+eps)) -------
__global__ void __launch_bounds__(128)
add_ln_kernel(const float* __restrict__ A, const float* __restrict__ Bv,
              const float* __restrict__ gamma, const float* __restrict__ beta,
              float* __restrict__ out)
{
    const int row = blockIdx.x;
    const int tid = threadIdx.x;
    __shared__ float red[4];

    const float4 a4 = reinterpret_cast<const float4*>(A  + (size_t)row * DMODEL)[tid];
    const float4 b4 = reinterpret_cast<const float4*>(Bv + (size_t)row * DMODEL)[tid];
    float x0 = a4.x + b4.x, x1 = a4.y + b4.y, x2 = a4.z + b4.z, x3 = a4.w + b4.w;

    float s = x0 + x1 + x2 + x3;
    #pragma unroll
    for (int off = 16; off; off >>= 1) s += __shfl_xor_sync(0xffffffffu, s, off);
    if ((tid & 31) == 0) red[tid >> 5] = s;
    __syncthreads();
    s = red[0] + red[1] + red[2] + red[3];
    const float mean = s * (1.0f / DMODEL);

    float d0 = x0 - mean, d1 = x1 - mean, d2 = x2 - mean, d3 = x3 - mean;
    float v = d0 * d0 + d1 * d1 + d2 * d2 + d3 * d3;
    #pragma unroll
    for (int off = 16; off; off >>= 1) v += __shfl_xor_sync(0xffffffffu, v, off);
    __syncthreads();
    if ((tid & 31) == 0) red[tid >> 5] = v;
    __syncthreads();
    v = (red[0] + red[1] + red[2] + red[3]) * (1.0f / DMODEL);

    const float inv = 1.0f / (sqrtf(v) + EPS);
    const float4 g4  = reinterpret_cast<const float4*>(gamma)[tid];
    const float4 be4 = reinterpret_cast<const float4*>(beta )[tid];
    float4 o4;
    o4.x = d0 * inv * g4.x + be4.x;
    o4.y = d1 * inv * g4.y + be4.y;
    o4.z = d2 * inv * g4.z + be4.z;
    o4.w = d3 * inv * g4.w + be4.w;
    reinterpret_cast<float4*>(out + (size_t)row * DMODEL)[tid] = o4;
}

// ---------------- host launch --------------------------------------------------
extern "C" void kernel_launch(void* const* d_in, const int* in_sizes, int n_in,
                              void* d_out, int out_size)
{
    const float* x   = (const float*)d_in[0];
    const float* Wq  = (const float*)d_in[1];
    const float* bq  = (const float*)d_in[2];
    const float* Wk  = (const float*)d_in[3];
    const float* bk  = (const float*)d_in[4];
    const float* Wv  = (const float*)d_in[5];
    const float* bv  = (const float*)d_in[6];
    const float* Wo  = (const float*)d_in[7];
    const float* bo  = (const float*)d_in[8];
    const float* W1  = (const float*)d_in[9];
    const float* b1  = (const float*)d_in[10];
    const float* W2  = (const float*)d_in[11];
    const float* b2  = (const float*)d_in[12];
    const float* g1  = (const float*)d_in[13];
    const float* be1 = (const float*)d_in[14];
    const float* g2  = (const float*)d_in[15];
    const float* be2 = (const float*)d_in[16];
    float* out = (float*)d_out;

    float *Qp, *Kp, *Vp, *AOp, *X1p, *FFHp;
    cudaGetSymbolAddress((void**)&Qp,   g_Q);
    cudaGetSymbolAddress((void**)&Kp,   g_K);
    cudaGetSymbolAddress((void**)&Vp,   g_V);
    cudaGetSymbolAddress((void**)&AOp,  g_AO);
    cudaGetSymbolAddress((void**)&X1p,  g_X1);
    cudaGetSymbolAddress((void**)&FFHp, g_FFH);

    cudaFuncSetAttribute(attn_tc, cudaFuncAttributeMaxDynamicSharedMemorySize, ATT_SMEM);
    cudaFuncSetAttribute(gemm_tc, cudaFuncAttributeMaxDynamicSharedMemorySize, GEMM_SMEM);
    cudaFuncSetAttribute(qkv_tc,  cudaFuncAttributeMaxDynamicSharedMemorySize, GEMM_SMEM);

    const dim3 t256(256), t128(128);
    const dim3 gQKV (DMODEL / TBN, ROWS / TBM, 3); // (4, 64, 3)
    const dim3 gProj(DMODEL / TBN, ROWS / TBM);    // (4, 64)
    const dim3 gFF1 (DFF    / TBN, ROWS / TBM);    // (16, 64)

    // QKV projections (fused launch)
    qkv_tc<<<gQKV, t256, GEMM_SMEM>>>(x, Wq, Wk, Wv, bq, bk, bv, Qp, Kp, Vp);

    // attention
    attn_tc<<<dim3(SEQ / QTILE, BATCH * NHEADS), t128, ATT_SMEM>>>(Qp, Kp, Vp, AOp);

    // output projection + LN1
    gemm_tc<<<gProj, t256, GEMM_SMEM>>>(AOp, Wo, bo, Qp, DMODEL, DMODEL, 0);
    add_ln_kernel<<<ROWS, 128>>>(x, Qp, g1, be1, X1p);

    // FFN
    gemm_tc<<<gFF1,  t256, GEMM_SMEM>>>(X1p,  W1, b1, FFHp, DFF,    DMODEL, 1);
    gemm_tc<<<gProj, t256, GEMM_SMEM>>>(FFHp, W2, b2, Kp,   DMODEL, DFF,    0);

    // LN2 -> final output
    add_ln_kernel<<<ROWS, 128>>>(X1p, Kp, g2, be2, out);
}